// round 1
// baseline (speedup 1.0000x reference)
#include <cuda_runtime.h>
#include <math.h>

#define B_  8
#define N_  1024
#define D_  1024
#define H_  16
#define DH_ 64
#define NEG_INF_ (-1e9f)

// Scratch (device globals — no allocation allowed)
__device__ float g_q[B_*N_*D_];
__device__ float g_k[B_*N_*D_];
__device__ float g_v[B_*N_*D_];
__device__ float g_ao[B_*N_*D_];

// ---------------------------------------------------------------------------
// Kernel 1: QKV projection.  C[8192,1024] = hid[8192,1024] @ W[1024,1024]
// blockIdx.z selects (Wq -> g_q), (Wk -> g_k), (Wv -> g_v)
// 128x128x8 tiles, 256 threads, 8x8 per thread, double-buffered smem.
// ---------------------------------------------------------------------------
__global__ __launch_bounds__(256) void qkv_gemm_kernel(
    const float* __restrict__ hid,
    const float* __restrict__ Wq,
    const float* __restrict__ Wk,
    const float* __restrict__ Wv)
{
    __shared__ float As[2][8][128];
    __shared__ float Bs[2][8][128];

    const int z = blockIdx.z;
    const float* W = (z == 0) ? Wq : (z == 1) ? Wk : Wv;
    float* C = (z == 0) ? g_q : (z == 1) ? g_k : g_v;

    const int m0 = blockIdx.y * 128;
    const int n0 = blockIdx.x * 128;
    const int tid = threadIdx.x;
    const int tx = tid & 15;
    const int ty = tid >> 4;

    const int ar = tid >> 1;          // 0..127 (A row within tile)
    const int ac = (tid & 1) * 4;     // 0 or 4 (A col within BK)
    const int br = tid >> 5;          // 0..7   (B row within BK)
    const int bc = (tid & 31) * 4;    // 0..124 (B col within tile)

    float acc[8][8];
    #pragma unroll
    for (int i = 0; i < 8; i++)
        #pragma unroll
        for (int j = 0; j < 8; j++) acc[i][j] = 0.f;

    // prefetch tile 0
    float4 a4 = *(const float4*)&hid[(long)(m0 + ar) * 1024 + ac];
    float4 b4 = *(const float4*)&W[(long)br * 1024 + n0 + bc];
    As[0][ac + 0][ar] = a4.x;
    As[0][ac + 1][ar] = a4.y;
    As[0][ac + 2][ar] = a4.z;
    As[0][ac + 3][ar] = a4.w;
    *(float4*)&Bs[0][br][bc] = b4;
    __syncthreads();

    int buf = 0;
    for (int kt = 0; kt < 128; kt++) {
        if (kt < 127) {
            int k0 = (kt + 1) * 8;
            a4 = *(const float4*)&hid[(long)(m0 + ar) * 1024 + k0 + ac];
            b4 = *(const float4*)&W[(long)(k0 + br) * 1024 + n0 + bc];
        }
        #pragma unroll
        for (int kk = 0; kk < 8; kk++) {
            float4 ra0 = *(const float4*)&As[buf][kk][ty * 8];
            float4 ra1 = *(const float4*)&As[buf][kk][ty * 8 + 4];
            float4 rb0 = *(const float4*)&Bs[buf][kk][tx * 8];
            float4 rb1 = *(const float4*)&Bs[buf][kk][tx * 8 + 4];
            float ra[8] = {ra0.x, ra0.y, ra0.z, ra0.w, ra1.x, ra1.y, ra1.z, ra1.w};
            float rb[8] = {rb0.x, rb0.y, rb0.z, rb0.w, rb1.x, rb1.y, rb1.z, rb1.w};
            #pragma unroll
            for (int i = 0; i < 8; i++)
                #pragma unroll
                for (int j = 0; j < 8; j++)
                    acc[i][j] = fmaf(ra[i], rb[j], acc[i][j]);
        }
        if (kt < 127) {
            int nb = buf ^ 1;
            As[nb][ac + 0][ar] = a4.x;
            As[nb][ac + 1][ar] = a4.y;
            As[nb][ac + 2][ar] = a4.z;
            As[nb][ac + 3][ar] = a4.w;
            *(float4*)&Bs[nb][br][bc] = b4;
            __syncthreads();
            buf = nb;
        }
    }

    #pragma unroll
    for (int i = 0; i < 8; i++) {
        long row = (long)(m0 + ty * 8 + i) * 1024 + n0 + tx * 8;
        float4 o0 = {acc[i][0], acc[i][1], acc[i][2], acc[i][3]};
        float4 o1 = {acc[i][4], acc[i][5], acc[i][6], acc[i][7]};
        *(float4*)&C[row] = o0;
        *(float4*)&C[row + 4] = o1;
    }
}

// ---------------------------------------------------------------------------
// Kernel 2: Flash attention with relative bias + adjacency mask.
// Grid: (N/128, H, B).  256 threads.  BQ=128, BKV=128, DH=64.
// ---------------------------------------------------------------------------
#define PS_STRIDE 132
// floats: Qs(64*128) + Ks(64*128) + Vs(128*64) + Ps(128*132) + red(128*16)
//         + mrow(128) + lrow(128) + srow(128) + table(8)
#define FLASH_SMEM_FLOATS (8192*3 + 128*PS_STRIDE + 128*16 + 128*3 + 8)
#define FLASH_SMEM_BYTES  (FLASH_SMEM_FLOATS * 4)

__global__ __launch_bounds__(256, 1) void flash_kernel(
    const int* __restrict__ adj,
    const int* __restrict__ relpos,
    const float* __restrict__ rel_table)
{
    extern __shared__ float sm[];
    float* Qs    = sm;                       // [64][128]  (d-major)
    float* Ks    = Qs + 64 * 128;            // [64][128]  (d-major)
    float* Vs    = Ks + 64 * 128;            // [128][64]  (k-major)
    float* Ps    = Vs + 128 * 64;            // [128][PS_STRIDE] (q-major)
    float* red   = Ps + 128 * PS_STRIDE;     // [128][16]
    float* mrow  = red + 128 * 16;
    float* lrow  = mrow + 128;
    float* srow  = lrow + 128;
    float* table = srow + 128;               // [8]

    const int q0 = blockIdx.x * 128;
    const int h  = blockIdx.y;
    const int b  = blockIdx.z;
    const int tid = threadIdx.x;
    const int tx = tid & 15;
    const int ty = tid >> 4;
    const int orow0 = ty * 8 + (tx >> 3) * 4;  // 4 O-rows
    const int oc0   = (tx & 7) * 8;            // 8 O-cols

    if (tid < 6) table[tid] = rel_table[tid];
    if (tid < 128) { mrow[tid] = -INFINITY; lrow[tid] = 0.f; }

    // Load Q (pre-scaled by 1/sqrt(D) = 1/32), transposed to d-major
    const float* qptr = g_q + ((long)b * N_ + q0) * D_ + h * DH_;
    const float scale = 0.03125f;
    #pragma unroll
    for (int it = 0; it < 8; it++) {
        int idx = tid + it * 256;          // 0..2047
        int qr = idx >> 4;                 // 0..127
        int d4 = (idx & 15) * 4;           // 0..60
        float4 v = *(const float4*)(qptr + (long)qr * D_ + d4);
        Qs[(d4 + 0) * 128 + qr] = v.x * scale;
        Qs[(d4 + 1) * 128 + qr] = v.y * scale;
        Qs[(d4 + 2) * 128 + qr] = v.z * scale;
        Qs[(d4 + 3) * 128 + qr] = v.w * scale;
    }

    float o[4][8];
    #pragma unroll
    for (int i = 0; i < 4; i++)
        #pragma unroll
        for (int j = 0; j < 8; j++) o[i][j] = 0.f;

    for (int kt = 0; kt < N_ / 128; kt++) {
        const int kv0 = kt * 128;
        __syncthreads();   // protect Ks/Vs/Ps/red reuse (and Qs stores on iter 0)

        // Load K (d-major) and V (k-major)
        const float* kptr = g_k + ((long)b * N_ + kv0) * D_ + h * DH_;
        const float* vptr = g_v + ((long)b * N_ + kv0) * D_ + h * DH_;
        #pragma unroll
        for (int it = 0; it < 8; it++) {
            int idx = tid + it * 256;
            int kr = idx >> 4;
            int d4 = (idx & 15) * 4;
            float4 kv = *(const float4*)(kptr + (long)kr * D_ + d4);
            Ks[(d4 + 0) * 128 + kr] = kv.x;
            Ks[(d4 + 1) * 128 + kr] = kv.y;
            Ks[(d4 + 2) * 128 + kr] = kv.z;
            Ks[(d4 + 3) * 128 + kr] = kv.w;
            float4 vv = *(const float4*)(vptr + (long)kr * D_ + d4);
            *(float4*)&Vs[kr * 64 + d4] = vv;
        }
        __syncthreads();

        // S = Q K^T  (8x8 per thread)
        float s[8][8];
        #pragma unroll
        for (int i = 0; i < 8; i++)
            #pragma unroll
            for (int j = 0; j < 8; j++) s[i][j] = 0.f;

        #pragma unroll 8
        for (int d = 0; d < 64; d++) {
            float4 qa = *(const float4*)&Qs[d * 128 + ty * 8];
            float4 qb = *(const float4*)&Qs[d * 128 + ty * 8 + 4];
            float4 ka = *(const float4*)&Ks[d * 128 + tx * 8];
            float4 kb = *(const float4*)&Ks[d * 128 + tx * 8 + 4];
            float ra[8] = {qa.x, qa.y, qa.z, qa.w, qb.x, qb.y, qb.z, qb.w};
            float rb[8] = {ka.x, ka.y, ka.z, ka.w, kb.x, kb.y, kb.z, kb.w};
            #pragma unroll
            for (int i = 0; i < 8; i++)
                #pragma unroll
                for (int j = 0; j < 8; j++)
                    s[i][j] = fmaf(ra[i], rb[j], s[i][j]);
        }

        // relative bias + adjacency mask
        #pragma unroll
        for (int i = 0; i < 8; i++) {
            long rowbase = ((long)b * N_ + (q0 + ty * 8 + i)) * N_ + kv0 + tx * 8;
            int4 a0 = *(const int4*)(adj + rowbase);
            int4 a1 = *(const int4*)(adj + rowbase + 4);
            int4 r0 = *(const int4*)(relpos + rowbase);
            int4 r1 = *(const int4*)(relpos + rowbase + 4);
            s[i][0] = a0.x ? s[i][0] + table[r0.x] : NEG_INF_;
            s[i][1] = a0.y ? s[i][1] + table[r0.y] : NEG_INF_;
            s[i][2] = a0.z ? s[i][2] + table[r0.z] : NEG_INF_;
            s[i][3] = a0.w ? s[i][3] + table[r0.w] : NEG_INF_;
            s[i][4] = a1.x ? s[i][4] + table[r1.x] : NEG_INF_;
            s[i][5] = a1.y ? s[i][5] + table[r1.y] : NEG_INF_;
            s[i][6] = a1.z ? s[i][6] + table[r1.z] : NEG_INF_;
            s[i][7] = a1.w ? s[i][7] + table[r1.w] : NEG_INF_;
        }

        // row-max partials
        #pragma unroll
        for (int i = 0; i < 8; i++) {
            float lm = s[i][0];
            #pragma unroll
            for (int j = 1; j < 8; j++) lm = fmaxf(lm, s[i][j]);
            red[(ty * 8 + i) * 16 + tx] = lm;
        }
        __syncthreads();

        if (tid < 128) {
            float tm = red[tid * 16];
            #pragma unroll
            for (int t = 1; t < 16; t++) tm = fmaxf(tm, red[tid * 16 + t]);
            float mo = mrow[tid];
            float mn = fmaxf(mo, tm);
            mrow[tid] = mn;
            float sc = __expf(mo - mn);
            srow[tid] = sc;
            lrow[tid] *= sc;
        }
        __syncthreads();

        // P = exp(S - m), store to smem (q-major), partial row sums
        #pragma unroll
        for (int i = 0; i < 8; i++) {
            float mn = mrow[ty * 8 + i];
            float p[8];
            float ls = 0.f;
            #pragma unroll
            for (int j = 0; j < 8; j++) {
                p[j] = __expf(s[i][j] - mn);
                ls += p[j];
            }
            float4 p0 = {p[0], p[1], p[2], p[3]};
            float4 p1 = {p[4], p[5], p[6], p[7]};
            *(float4*)&Ps[(ty * 8 + i) * PS_STRIDE + tx * 8] = p0;
            *(float4*)&Ps[(ty * 8 + i) * PS_STRIDE + tx * 8 + 4] = p1;
            red[(ty * 8 + i) * 16 + tx] = ls;
        }
        // rescale O accumulators
        #pragma unroll
        for (int i = 0; i < 4; i++) {
            float sc = srow[orow0 + i];
            #pragma unroll
            for (int j = 0; j < 8; j++) o[i][j] *= sc;
        }
        __syncthreads();

        if (tid < 128) {
            float t = 0.f;
            #pragma unroll
            for (int k = 0; k < 16; k++) t += red[tid * 16 + k];
            lrow[tid] += t;
        }

        // O += P V   (4x8 per thread, k vectorized by 4)
        #pragma unroll 2
        for (int k4 = 0; k4 < 128; k4 += 4) {
            float prf[4][4];
            #pragma unroll
            for (int i = 0; i < 4; i++)
                *(float4*)prf[i] = *(const float4*)&Ps[(orow0 + i) * PS_STRIDE + k4];
            #pragma unroll
            for (int kk = 0; kk < 4; kk++) {
                float4 v0 = *(const float4*)&Vs[(k4 + kk) * 64 + oc0];
                float4 v1 = *(const float4*)&Vs[(k4 + kk) * 64 + oc0 + 4];
                #pragma unroll
                for (int i = 0; i < 4; i++) {
                    float pk = prf[i][kk];
                    o[i][0] = fmaf(pk, v0.x, o[i][0]);
                    o[i][1] = fmaf(pk, v0.y, o[i][1]);
                    o[i][2] = fmaf(pk, v0.z, o[i][2]);
                    o[i][3] = fmaf(pk, v0.w, o[i][3]);
                    o[i][4] = fmaf(pk, v1.x, o[i][4]);
                    o[i][5] = fmaf(pk, v1.y, o[i][5]);
                    o[i][6] = fmaf(pk, v1.z, o[i][6]);
                    o[i][7] = fmaf(pk, v1.w, o[i][7]);
                }
            }
        }
    }
    __syncthreads();  // lrow finalized

    float* aout = g_ao + ((long)b * N_ + q0) * D_ + h * DH_;
    #pragma unroll
    for (int i = 0; i < 4; i++) {
        float inv = 1.f / lrow[orow0 + i];
        float4 r0 = {o[i][0] * inv, o[i][1] * inv, o[i][2] * inv, o[i][3] * inv};
        float4 r1 = {o[i][4] * inv, o[i][5] * inv, o[i][6] * inv, o[i][7] * inv};
        *(float4*)(aout + (long)(orow0 + i) * D_ + oc0) = r0;
        *(float4*)(aout + (long)(orow0 + i) * D_ + oc0 + 4) = r1;
    }
}

// ---------------------------------------------------------------------------
// Kernel 3: out = LayerNorm(relu(attn_out) + hid) * gamma + beta
// one CTA per row (8192 rows), 256 threads, 4 floats each.
// ---------------------------------------------------------------------------
__global__ __launch_bounds__(256) void epilogue_kernel(
    const float* __restrict__ hid,
    const float* __restrict__ gamma,
    const float* __restrict__ beta,
    float* __restrict__ out)
{
    __shared__ float rs[8];
    __shared__ float rq[8];
    __shared__ float stats[2];

    const long row = blockIdx.x;
    const float* a = g_ao + row * D_;
    const float* hp = hid + row * D_;
    const int c = threadIdx.x * 4;

    float4 av = *(const float4*)(a + c);
    float4 hv = *(const float4*)(hp + c);
    float4 y;
    y.x = fmaxf(av.x, 0.f) + hv.x;
    y.y = fmaxf(av.y, 0.f) + hv.y;
    y.z = fmaxf(av.z, 0.f) + hv.z;
    y.w = fmaxf(av.w, 0.f) + hv.w;

    float sum = y.x + y.y + y.z + y.w;
    float sq  = y.x * y.x + y.y * y.y + y.z * y.z + y.w * y.w;
    #pragma unroll
    for (int off = 16; off > 0; off >>= 1) {
        sum += __shfl_xor_sync(0xffffffffu, sum, off);
        sq  += __shfl_xor_sync(0xffffffffu, sq, off);
    }
    if ((threadIdx.x & 31) == 0) {
        rs[threadIdx.x >> 5] = sum;
        rq[threadIdx.x >> 5] = sq;
    }
    __syncthreads();
    if (threadIdx.x == 0) {
        float S = 0.f, Q = 0.f;
        #pragma unroll
        for (int w = 0; w < 8; w++) { S += rs[w]; Q += rq[w]; }
        float mean = S * (1.f / 1024.f);
        float var  = Q * (1.f / 1024.f) - mean * mean;
        stats[0] = mean;
        stats[1] = rsqrtf(var + 1e-5f);
    }
    __syncthreads();
    float mean = stats[0], rstd = stats[1];

    float4 g4 = *(const float4*)(gamma + c);
    float4 b4 = *(const float4*)(beta + c);
    float4 o4;
    o4.x = (y.x - mean) * rstd * g4.x + b4.x;
    o4.y = (y.y - mean) * rstd * g4.y + b4.y;
    o4.z = (y.z - mean) * rstd * g4.z + b4.z;
    o4.w = (y.w - mean) * rstd * g4.w + b4.w;
    *(float4*)(out + row * D_ + c) = o4;
}

// ---------------------------------------------------------------------------
extern "C" void kernel_launch(void* const* d_in, const int* in_sizes, int n_in,
                              void* d_out, int out_size)
{
    const float* hid      = (const float*)d_in[0];
    const int*   adj      = (const int*)d_in[1];
    const int*   relpos   = (const int*)d_in[2];
    const float* Wq       = (const float*)d_in[3];
    const float* Wk       = (const float*)d_in[4];
    const float* Wv       = (const float*)d_in[5];
    const float* rel_tab  = (const float*)d_in[6];
    const float* gamma    = (const float*)d_in[7];
    const float* beta     = (const float*)d_in[8];
    float* out = (float*)d_out;

    dim3 ggrid(1024 / 128, 8192 / 128, 3);
    qkv_gemm_kernel<<<ggrid, 256>>>(hid, Wq, Wk, Wv);

    cudaFuncSetAttribute(flash_kernel,
                         cudaFuncAttributeMaxDynamicSharedMemorySize,
                         FLASH_SMEM_BYTES);
    dim3 fgrid(N_ / 128, H_, B_);
    flash_kernel<<<fgrid, 256, FLASH_SMEM_BYTES>>>(adj, relpos, rel_tab);

    epilogue_kernel<<<B_ * N_, 256>>>(hid, gamma, beta, out);
}

// round 3
// speedup vs baseline: 1.3958x; 1.3958x over previous
#include <cuda_runtime.h>
#include <cuda_bf16.h>
#include <cstdint>
#include <math.h>

#define B_  8
#define N_  1024
#define D_  1024
#define H_  16
#define DH_ 64
#define NEG_INF_ (-1e9f)

// Scratch (device globals — no allocation allowed)
__device__ float g_q[B_*N_*D_];
__device__ float g_k[B_*N_*D_];
__device__ float g_v[B_*N_*D_];
__device__ float g_ao[B_*N_*D_];

// ---------------------------------------------------------------------------
// Kernel 1: QKV projection with bf16-split tensor-core MMA.
// C[8192,1024] = hid[8192,1024] @ W[1024,1024], z selects Wq/Wk/Wv.
// CTA tile 128x128, BK=32, 8 warps (64x32 each), mma.m16n8k16 bf16,
// 3-pass split (hi*hi + hi*lo + lo*hi) for ~fp32 accuracy.
// ---------------------------------------------------------------------------
#define AW_ 136                    // 32-bit words per kp-row (128 used + 8 pad)
#define QUAD_ (16 * AW_)           // one array (16 kp rows)
#define BUFW_ (4 * QUAD_)          // Ah, Al, Bh, Bl
#define GEMM_SMEM_BYTES (2 * BUFW_ * 4)

__device__ __forceinline__ uint32_t pack_bf16(float x, float y) {
    __nv_bfloat162 t = __floats2bfloat162_rn(x, y);
    return *(uint32_t*)&t;
}
__device__ __forceinline__ void split_bf16(float x, float& hi, float& lo) {
    __nv_bfloat16 h = __float2bfloat16_rn(x);
    hi = __bfloat162float(h);
    lo = x - hi;
}
__device__ __forceinline__ void mma_bf16(float* d, const uint32_t* a, const uint32_t* b) {
    asm volatile(
        "mma.sync.aligned.m16n8k16.row.col.f32.bf16.bf16.f32 "
        "{%0,%1,%2,%3}, {%4,%5,%6,%7}, {%8,%9}, {%0,%1,%2,%3};\n"
        : "+f"(d[0]), "+f"(d[1]), "+f"(d[2]), "+f"(d[3])
        : "r"(a[0]), "r"(a[1]), "r"(a[2]), "r"(a[3]), "r"(b[0]), "r"(b[1]));
}

__global__ __launch_bounds__(256, 1) void qkv_gemm_kernel(
    const float* __restrict__ hid,
    const float* __restrict__ Wq,
    const float* __restrict__ Wk,
    const float* __restrict__ Wv)
{
    extern __shared__ uint32_t sm32[];

    const int z = blockIdx.z;
    const float* W = (z == 0) ? Wq : (z == 1) ? Wk : Wv;
    float* C = (z == 0) ? g_q : (z == 1) ? g_k : g_v;

    const int m0 = blockIdx.y * 128;
    const int n0 = blockIdx.x * 128;
    const int tid = threadIdx.x;
    const int lane = tid & 31;
    const int warp = tid >> 5;
    const int wm = warp & 1;        // 2 warps in M (64 rows each)
    const int wn = warp >> 1;       // 4 warps in N (32 cols each)

    // Global-load mapping
    const int rA = tid >> 3;        // 0..31  (A row base; rows rA + 32j)
    const int fA = tid & 7;         // float4 col index within BK=32
    const int n4 = tid & 31;        // B: float4 col index within 128 cols
    const int kp2 = tid >> 5;       // B: k-pair group (handles kp2, kp2+8)

    float acc[4][4][4];
    #pragma unroll
    for (int i = 0; i < 4; i++)
        #pragma unroll
        for (int j = 0; j < 4; j++)
            #pragma unroll
            for (int r = 0; r < 4; r++) acc[i][j][r] = 0.f;

    float4 pa[4], pb[4];

    // prefetch chunk 0
    #pragma unroll
    for (int j = 0; j < 4; j++)
        pa[j] = *(const float4*)&hid[(long)(m0 + rA + 32 * j) * 1024 + fA * 4];
    #pragma unroll
    for (int t = 0; t < 2; t++) {
        int kp = kp2 + 8 * t;
        pb[2 * t + 0] = *(const float4*)&W[(long)(2 * kp + 0) * 1024 + n0 + n4 * 4];
        pb[2 * t + 1] = *(const float4*)&W[(long)(2 * kp + 1) * 1024 + n0 + n4 * 4];
    }

    int buf = 0;
    // store chunk 0
    {
        uint32_t* Ah = sm32;            uint32_t* Al = sm32 + QUAD_;
        uint32_t* Bh = sm32 + 2*QUAD_;  uint32_t* Bl = sm32 + 3*QUAD_;
        #pragma unroll
        for (int j = 0; j < 4; j++) {
            float hx, lx, hy, ly, hz, lz, hw, lw;
            split_bf16(pa[j].x, hx, lx); split_bf16(pa[j].y, hy, ly);
            split_bf16(pa[j].z, hz, lz); split_bf16(pa[j].w, hw, lw);
            int r = rA + 32 * j;
            Ah[(fA*2 + 0) * AW_ + r] = pack_bf16(hx, hy);
            Ah[(fA*2 + 1) * AW_ + r] = pack_bf16(hz, hw);
            Al[(fA*2 + 0) * AW_ + r] = pack_bf16(lx, ly);
            Al[(fA*2 + 1) * AW_ + r] = pack_bf16(lz, lw);
        }
        #pragma unroll
        for (int t = 0; t < 2; t++) {
            int kp = kp2 + 8 * t;
            float4 e = pb[2*t], o = pb[2*t+1];
            float he[4], le[4], ho[4], lo_[4];
            split_bf16(e.x, he[0], le[0]); split_bf16(e.y, he[1], le[1]);
            split_bf16(e.z, he[2], le[2]); split_bf16(e.w, he[3], le[3]);
            split_bf16(o.x, ho[0], lo_[0]); split_bf16(o.y, ho[1], lo_[1]);
            split_bf16(o.z, ho[2], lo_[2]); split_bf16(o.w, ho[3], lo_[3]);
            uint4 wh, wl;
            wh.x = pack_bf16(he[0], ho[0]); wh.y = pack_bf16(he[1], ho[1]);
            wh.z = pack_bf16(he[2], ho[2]); wh.w = pack_bf16(he[3], ho[3]);
            wl.x = pack_bf16(le[0], lo_[0]); wl.y = pack_bf16(le[1], lo_[1]);
            wl.z = pack_bf16(le[2], lo_[2]); wl.w = pack_bf16(le[3], lo_[3]);
            *(uint4*)&Bh[kp * AW_ + n4 * 4] = wh;
            *(uint4*)&Bl[kp * AW_ + n4 * 4] = wl;
        }
    }
    __syncthreads();

    const int kq = lane & 3;        // k-pair within k16
    const int ml = lane >> 2;       // 0..7

    for (int kt = 0; kt < 32; kt++) {
        // prefetch next chunk
        if (kt < 31) {
            int k0 = (kt + 1) * 32;
            #pragma unroll
            for (int j = 0; j < 4; j++)
                pa[j] = *(const float4*)&hid[(long)(m0 + rA + 32 * j) * 1024 + k0 + fA * 4];
            #pragma unroll
            for (int t = 0; t < 2; t++) {
                int kp = kp2 + 8 * t;
                pb[2*t+0] = *(const float4*)&W[(long)(k0 + 2*kp + 0) * 1024 + n0 + n4 * 4];
                pb[2*t+1] = *(const float4*)&W[(long)(k0 + 2*kp + 1) * 1024 + n0 + n4 * 4];
            }
        }

        uint32_t* base = sm32 + buf * BUFW_;
        uint32_t* Ah = base;             uint32_t* Al = base + QUAD_;
        uint32_t* Bh = base + 2*QUAD_;   uint32_t* Bl = base + 3*QUAD_;

        #pragma unroll
        for (int ks = 0; ks < 2; ks++) {
            const int kb = ks * 8;
            uint32_t ah[4][4], al[4][4], bh[4][2], bl[4][2];
            #pragma unroll
            for (int i = 0; i < 4; i++) {
                int mr = wm * 64 + i * 16 + ml;
                ah[i][0] = Ah[(kb + kq) * AW_ + mr];
                ah[i][1] = Ah[(kb + kq) * AW_ + mr + 8];
                ah[i][2] = Ah[(kb + kq + 4) * AW_ + mr];
                ah[i][3] = Ah[(kb + kq + 4) * AW_ + mr + 8];
                al[i][0] = Al[(kb + kq) * AW_ + mr];
                al[i][1] = Al[(kb + kq) * AW_ + mr + 8];
                al[i][2] = Al[(kb + kq + 4) * AW_ + mr];
                al[i][3] = Al[(kb + kq + 4) * AW_ + mr + 8];
            }
            #pragma unroll
            for (int j = 0; j < 4; j++) {
                int nc = wn * 32 + j * 8 + ml;
                bh[j][0] = Bh[(kb + kq) * AW_ + nc];
                bh[j][1] = Bh[(kb + kq + 4) * AW_ + nc];
                bl[j][0] = Bl[(kb + kq) * AW_ + nc];
                bl[j][1] = Bl[(kb + kq + 4) * AW_ + nc];
            }
            #pragma unroll
            for (int i = 0; i < 4; i++)
                #pragma unroll
                for (int j = 0; j < 4; j++) {
                    mma_bf16(acc[i][j], ah[i], bh[j]);
                    mma_bf16(acc[i][j], ah[i], bl[j]);
                    mma_bf16(acc[i][j], al[i], bh[j]);
                }
        }

        // store next chunk into other buffer
        if (kt < 31) {
            uint32_t* nb = sm32 + (buf ^ 1) * BUFW_;
            uint32_t* nAh = nb;             uint32_t* nAl = nb + QUAD_;
            uint32_t* nBh = nb + 2*QUAD_;   uint32_t* nBl = nb + 3*QUAD_;
            #pragma unroll
            for (int j = 0; j < 4; j++) {
                float hx, lx, hy, ly, hz, lz, hw, lw;
                split_bf16(pa[j].x, hx, lx); split_bf16(pa[j].y, hy, ly);
                split_bf16(pa[j].z, hz, lz); split_bf16(pa[j].w, hw, lw);
                int r = rA + 32 * j;
                nAh[(fA*2 + 0) * AW_ + r] = pack_bf16(hx, hy);
                nAh[(fA*2 + 1) * AW_ + r] = pack_bf16(hz, hw);
                nAl[(fA*2 + 0) * AW_ + r] = pack_bf16(lx, ly);
                nAl[(fA*2 + 1) * AW_ + r] = pack_bf16(lz, lw);
            }
            #pragma unroll
            for (int t = 0; t < 2; t++) {
                int kp = kp2 + 8 * t;
                float4 e = pb[2*t], o = pb[2*t+1];
                float he[4], le[4], ho[4], lo_[4];
                split_bf16(e.x, he[0], le[0]); split_bf16(e.y, he[1], le[1]);
                split_bf16(e.z, he[2], le[2]); split_bf16(e.w, he[3], le[3]);
                split_bf16(o.x, ho[0], lo_[0]); split_bf16(o.y, ho[1], lo_[1]);
                split_bf16(o.z, ho[2], lo_[2]); split_bf16(o.w, ho[3], lo_[3]);
                uint4 wh, wl;
                wh.x = pack_bf16(he[0], ho[0]); wh.y = pack_bf16(he[1], ho[1]);
                wh.z = pack_bf16(he[2], ho[2]); wh.w = pack_bf16(he[3], ho[3]);
                wl.x = pack_bf16(le[0], lo_[0]); wl.y = pack_bf16(le[1], lo_[1]);
                wl.z = pack_bf16(le[2], lo_[2]); wl.w = pack_bf16(le[3], lo_[3]);
                *(uint4*)&nBh[kp * AW_ + n4 * 4] = wh;
                *(uint4*)&nBl[kp * AW_ + n4 * 4] = wl;
            }
            __syncthreads();
            buf ^= 1;
        }
    }

    // write back C
    #pragma unroll
    for (int i = 0; i < 4; i++) {
        #pragma unroll
        for (int j = 0; j < 4; j++) {
            int row = m0 + wm * 64 + i * 16 + (lane >> 2);
            int col = n0 + wn * 32 + j * 8 + (lane & 3) * 2;
            float2 c01 = {acc[i][j][0], acc[i][j][1]};
            float2 c23 = {acc[i][j][2], acc[i][j][3]};
            *(float2*)&C[(long)row * 1024 + col] = c01;
            *(float2*)&C[(long)(row + 8) * 1024 + col] = c23;
        }
    }
}

// ---------------------------------------------------------------------------
// Kernel 2: Flash attention with relative bias + adjacency mask. (fp32 SIMT)
// Grid: (N/128, H, B).  256 threads.  BQ=128, BKV=128, DH=64.
// ---------------------------------------------------------------------------
#define PS_STRIDE 132
#define FLASH_SMEM_FLOATS (8192*3 + 128*PS_STRIDE + 128*16 + 128*3 + 8)
#define FLASH_SMEM_BYTES  (FLASH_SMEM_FLOATS * 4)

__global__ __launch_bounds__(256, 1) void flash_kernel(
    const int* __restrict__ adj,
    const int* __restrict__ relpos,
    const float* __restrict__ rel_table)
{
    extern __shared__ float sm[];
    float* Qs    = sm;                       // [64][128]  (d-major)
    float* Ks    = Qs + 64 * 128;            // [64][128]  (d-major)
    float* Vs    = Ks + 64 * 128;            // [128][64]  (k-major)
    float* Ps    = Vs + 128 * 64;            // [128][PS_STRIDE] (q-major)
    float* red   = Ps + 128 * PS_STRIDE;     // [128][16]
    float* mrow  = red + 128 * 16;
    float* lrow  = mrow + 128;
    float* srow  = lrow + 128;
    float* table = srow + 128;               // [8]

    const int q0 = blockIdx.x * 128;
    const int h  = blockIdx.y;
    const int b  = blockIdx.z;
    const int tid = threadIdx.x;
    const int tx = tid & 15;
    const int ty = tid >> 4;
    const int orow0 = ty * 8 + (tx >> 3) * 4;  // 4 O-rows
    const int oc0   = (tx & 7) * 8;            // 8 O-cols

    if (tid < 6) table[tid] = rel_table[tid];
    if (tid < 128) { mrow[tid] = -INFINITY; lrow[tid] = 0.f; }

    const float* qptr = g_q + ((long)b * N_ + q0) * D_ + h * DH_;
    const float scale = 0.03125f;
    #pragma unroll
    for (int it = 0; it < 8; it++) {
        int idx = tid + it * 256;
        int qr = idx >> 4;
        int d4 = (idx & 15) * 4;
        float4 v = *(const float4*)(qptr + (long)qr * D_ + d4);
        Qs[(d4 + 0) * 128 + qr] = v.x * scale;
        Qs[(d4 + 1) * 128 + qr] = v.y * scale;
        Qs[(d4 + 2) * 128 + qr] = v.z * scale;
        Qs[(d4 + 3) * 128 + qr] = v.w * scale;
    }

    float o[4][8];
    #pragma unroll
    for (int i = 0; i < 4; i++)
        #pragma unroll
        for (int j = 0; j < 8; j++) o[i][j] = 0.f;

    for (int kt = 0; kt < N_ / 128; kt++) {
        const int kv0 = kt * 128;
        __syncthreads();

        const float* kptr = g_k + ((long)b * N_ + kv0) * D_ + h * DH_;
        const float* vptr = g_v + ((long)b * N_ + kv0) * D_ + h * DH_;
        #pragma unroll
        for (int it = 0; it < 8; it++) {
            int idx = tid + it * 256;
            int kr = idx >> 4;
            int d4 = (idx & 15) * 4;
            float4 kv = *(const float4*)(kptr + (long)kr * D_ + d4);
            Ks[(d4 + 0) * 128 + kr] = kv.x;
            Ks[(d4 + 1) * 128 + kr] = kv.y;
            Ks[(d4 + 2) * 128 + kr] = kv.z;
            Ks[(d4 + 3) * 128 + kr] = kv.w;
            float4 vv = *(const float4*)(vptr + (long)kr * D_ + d4);
            *(float4*)&Vs[kr * 64 + d4] = vv;
        }
        __syncthreads();

        float s[8][8];
        #pragma unroll
        for (int i = 0; i < 8; i++)
            #pragma unroll
            for (int j = 0; j < 8; j++) s[i][j] = 0.f;

        #pragma unroll 8
        for (int d = 0; d < 64; d++) {
            float4 qa = *(const float4*)&Qs[d * 128 + ty * 8];
            float4 qb = *(const float4*)&Qs[d * 128 + ty * 8 + 4];
            float4 ka = *(const float4*)&Ks[d * 128 + tx * 8];
            float4 kb = *(const float4*)&Ks[d * 128 + tx * 8 + 4];
            float ra[8] = {qa.x, qa.y, qa.z, qa.w, qb.x, qb.y, qb.z, qb.w};
            float rb[8] = {ka.x, ka.y, ka.z, ka.w, kb.x, kb.y, kb.z, kb.w};
            #pragma unroll
            for (int i = 0; i < 8; i++)
                #pragma unroll
                for (int j = 0; j < 8; j++)
                    s[i][j] = fmaf(ra[i], rb[j], s[i][j]);
        }

        #pragma unroll
        for (int i = 0; i < 8; i++) {
            long rowbase = ((long)b * N_ + (q0 + ty * 8 + i)) * N_ + kv0 + tx * 8;
            int4 a0 = *(const int4*)(adj + rowbase);
            int4 a1 = *(const int4*)(adj + rowbase + 4);
            int4 r0 = *(const int4*)(relpos + rowbase);
            int4 r1 = *(const int4*)(relpos + rowbase + 4);
            s[i][0] = a0.x ? s[i][0] + table[r0.x] : NEG_INF_;
            s[i][1] = a0.y ? s[i][1] + table[r0.y] : NEG_INF_;
            s[i][2] = a0.z ? s[i][2] + table[r0.z] : NEG_INF_;
            s[i][3] = a0.w ? s[i][3] + table[r0.w] : NEG_INF_;
            s[i][4] = a1.x ? s[i][4] + table[r1.x] : NEG_INF_;
            s[i][5] = a1.y ? s[i][5] + table[r1.y] : NEG_INF_;
            s[i][6] = a1.z ? s[i][6] + table[r1.z] : NEG_INF_;
            s[i][7] = a1.w ? s[i][7] + table[r1.w] : NEG_INF_;
        }

        #pragma unroll
        for (int i = 0; i < 8; i++) {
            float lm = s[i][0];
            #pragma unroll
            for (int j = 1; j < 8; j++) lm = fmaxf(lm, s[i][j]);
            red[(ty * 8 + i) * 16 + tx] = lm;
        }
        __syncthreads();

        if (tid < 128) {
            float tm = red[tid * 16];
            #pragma unroll
            for (int t = 1; t < 16; t++) tm = fmaxf(tm, red[tid * 16 + t]);
            float mo = mrow[tid];
            float mn = fmaxf(mo, tm);
            mrow[tid] = mn;
            float sc = __expf(mo - mn);
            srow[tid] = sc;
            lrow[tid] *= sc;
        }
        __syncthreads();

        #pragma unroll
        for (int i = 0; i < 8; i++) {
            float mn = mrow[ty * 8 + i];
            float p[8];
            float ls = 0.f;
            #pragma unroll
            for (int j = 0; j < 8; j++) {
                p[j] = __expf(s[i][j] - mn);
                ls += p[j];
            }
            float4 p0 = {p[0], p[1], p[2], p[3]};
            float4 p1 = {p[4], p[5], p[6], p[7]};
            *(float4*)&Ps[(ty * 8 + i) * PS_STRIDE + tx * 8] = p0;
            *(float4*)&Ps[(ty * 8 + i) * PS_STRIDE + tx * 8 + 4] = p1;
            red[(ty * 8 + i) * 16 + tx] = ls;
        }
        #pragma unroll
        for (int i = 0; i < 4; i++) {
            float sc = srow[orow0 + i];
            #pragma unroll
            for (int j = 0; j < 8; j++) o[i][j] *= sc;
        }
        __syncthreads();

        if (tid < 128) {
            float t = 0.f;
            #pragma unroll
            for (int k = 0; k < 16; k++) t += red[tid * 16 + k];
            lrow[tid] += t;
        }

        #pragma unroll 2
        for (int k4 = 0; k4 < 128; k4 += 4) {
            float prf[4][4];
            #pragma unroll
            for (int i = 0; i < 4; i++)
                *(float4*)prf[i] = *(const float4*)&Ps[(orow0 + i) * PS_STRIDE + k4];
            #pragma unroll
            for (int kk = 0; kk < 4; kk++) {
                float4 v0 = *(const float4*)&Vs[(k4 + kk) * 64 + oc0];
                float4 v1 = *(const float4*)&Vs[(k4 + kk) * 64 + oc0 + 4];
                #pragma unroll
                for (int i = 0; i < 4; i++) {
                    float pk = prf[i][kk];
                    o[i][0] = fmaf(pk, v0.x, o[i][0]);
                    o[i][1] = fmaf(pk, v0.y, o[i][1]);
                    o[i][2] = fmaf(pk, v0.z, o[i][2]);
                    o[i][3] = fmaf(pk, v0.w, o[i][3]);
                    o[i][4] = fmaf(pk, v1.x, o[i][4]);
                    o[i][5] = fmaf(pk, v1.y, o[i][5]);
                    o[i][6] = fmaf(pk, v1.z, o[i][6]);
                    o[i][7] = fmaf(pk, v1.w, o[i][7]);
                }
            }
        }
    }
    __syncthreads();

    float* aout = g_ao + ((long)b * N_ + q0) * D_ + h * DH_;
    #pragma unroll
    for (int i = 0; i < 4; i++) {
        float inv = 1.f / lrow[orow0 + i];
        float4 r0 = {o[i][0] * inv, o[i][1] * inv, o[i][2] * inv, o[i][3] * inv};
        float4 r1 = {o[i][4] * inv, o[i][5] * inv, o[i][6] * inv, o[i][7] * inv};
        *(float4*)(aout + (long)(orow0 + i) * D_ + oc0) = r0;
        *(float4*)(aout + (long)(orow0 + i) * D_ + oc0 + 4) = r1;
    }
}

// ---------------------------------------------------------------------------
// Kernel 3: out = LayerNorm(relu(attn_out) + hid) * gamma + beta
// ---------------------------------------------------------------------------
__global__ __launch_bounds__(256) void epilogue_kernel(
    const float* __restrict__ hid,
    const float* __restrict__ gamma,
    const float* __restrict__ beta,
    float* __restrict__ out)
{
    __shared__ float rs[8];
    __shared__ float rq[8];
    __shared__ float stats[2];

    const long row = blockIdx.x;
    const float* a = g_ao + row * D_;
    const float* hp = hid + row * D_;
    const int c = threadIdx.x * 4;

    float4 av = *(const float4*)(a + c);
    float4 hv = *(const float4*)(hp + c);
    float4 y;
    y.x = fmaxf(av.x, 0.f) + hv.x;
    y.y = fmaxf(av.y, 0.f) + hv.y;
    y.z = fmaxf(av.z, 0.f) + hv.z;
    y.w = fmaxf(av.w, 0.f) + hv.w;

    float sum = y.x + y.y + y.z + y.w;
    float sq  = y.x * y.x + y.y * y.y + y.z * y.z + y.w * y.w;
    #pragma unroll
    for (int off = 16; off > 0; off >>= 1) {
        sum += __shfl_xor_sync(0xffffffffu, sum, off);
        sq  += __shfl_xor_sync(0xffffffffu, sq, off);
    }
    if ((threadIdx.x & 31) == 0) {
        rs[threadIdx.x >> 5] = sum;
        rq[threadIdx.x >> 5] = sq;
    }
    __syncthreads();
    if (threadIdx.x == 0) {
        float S = 0.f, Q = 0.f;
        #pragma unroll
        for (int w = 0; w < 8; w++) { S += rs[w]; Q += rq[w]; }
        float mean = S * (1.f / 1024.f);
        float var  = Q * (1.f / 1024.f) - mean * mean;
        stats[0] = mean;
        stats[1] = rsqrtf(var + 1e-5f);
    }
    __syncthreads();
    float mean = stats[0], rstd = stats[1];

    float4 g4 = *(const float4*)(gamma + c);
    float4 b4 = *(const float4*)(beta + c);
    float4 o4;
    o4.x = (y.x - mean) * rstd * g4.x + b4.x;
    o4.y = (y.y - mean) * rstd * g4.y + b4.y;
    o4.z = (y.z - mean) * rstd * g4.z + b4.z;
    o4.w = (y.w - mean) * rstd * g4.w + b4.w;
    *(float4*)(out + row * D_ + c) = o4;
}

// ---------------------------------------------------------------------------
extern "C" void kernel_launch(void* const* d_in, const int* in_sizes, int n_in,
                              void* d_out, int out_size)
{
    const float* hid      = (const float*)d_in[0];
    const int*   adj      = (const int*)d_in[1];
    const int*   relpos   = (const int*)d_in[2];
    const float* Wq       = (const float*)d_in[3];
    const float* Wk       = (const float*)d_in[4];
    const float* Wv       = (const float*)d_in[5];
    const float* rel_tab  = (const float*)d_in[6];
    const float* gamma    = (const float*)d_in[7];
    const float* beta     = (const float*)d_in[8];
    float* out = (float*)d_out;

    cudaFuncSetAttribute(qkv_gemm_kernel,
                         cudaFuncAttributeMaxDynamicSharedMemorySize,
                         GEMM_SMEM_BYTES);
    dim3 ggrid(1024 / 128, 8192 / 128, 3);
    qkv_gemm_kernel<<<ggrid, 256, GEMM_SMEM_BYTES>>>(hid, Wq, Wk, Wv);

    cudaFuncSetAttribute(flash_kernel,
                         cudaFuncAttributeMaxDynamicSharedMemorySize,
                         FLASH_SMEM_BYTES);
    dim3 fgrid(N_ / 128, H_, B_);
    flash_kernel<<<fgrid, 256, FLASH_SMEM_BYTES>>>(adj, relpos, rel_tab);

    epilogue_kernel<<<B_ * N_, 256>>>(hid, gamma, beta, out);
}

// round 4
// speedup vs baseline: 1.5560x; 1.1148x over previous
#include <cuda_runtime.h>
#include <cuda_bf16.h>
#include <cstdint>
#include <math.h>

#define B_  8
#define N_  1024
#define D_  1024
#define H_  16
#define DH_ 64
#define NEG_INF_ (-1e9f)

// Scratch (device globals — no allocation allowed)
__device__ float g_q[B_*N_*D_];
__device__ float g_k[B_*N_*D_];
__device__ float g_v[B_*N_*D_];
__device__ float g_ao[B_*N_*D_];

// ---------------------------------------------------------------------------
// Shared helpers: bf16 split + m16n8k16 mma
// ---------------------------------------------------------------------------
__device__ __forceinline__ uint32_t pack_bf16(float x, float y) {
    __nv_bfloat162 t = __floats2bfloat162_rn(x, y);
    return *(uint32_t*)&t;
}
__device__ __forceinline__ void split_bf16(float x, float& hi, float& lo) {
    __nv_bfloat16 h = __float2bfloat16_rn(x);
    hi = __bfloat162float(h);
    lo = x - hi;
}
__device__ __forceinline__ void split2_pack(float x, float y, uint32_t& hi, uint32_t& lo) {
    float hx, lx, hy, ly;
    split_bf16(x, hx, lx); split_bf16(y, hy, ly);
    hi = pack_bf16(hx, hy); lo = pack_bf16(lx, ly);
}
__device__ __forceinline__ void mma_bf16(float* d, const uint32_t* a, const uint32_t* b) {
    asm volatile(
        "mma.sync.aligned.m16n8k16.row.col.f32.bf16.bf16.f32 "
        "{%0,%1,%2,%3}, {%4,%5,%6,%7}, {%8,%9}, {%0,%1,%2,%3};\n"
        : "+f"(d[0]), "+f"(d[1]), "+f"(d[2]), "+f"(d[3])
        : "r"(a[0]), "r"(a[1]), "r"(a[2]), "r"(a[3]), "r"(b[0]), "r"(b[1]));
}

// ---------------------------------------------------------------------------
// Kernel 1: QKV projection with bf16-split tensor-core MMA. (unchanged R3)
// ---------------------------------------------------------------------------
#define AW_ 136
#define QUAD_ (16 * AW_)
#define BUFW_ (4 * QUAD_)
#define GEMM_SMEM_BYTES (2 * BUFW_ * 4)

__global__ __launch_bounds__(256, 1) void qkv_gemm_kernel(
    const float* __restrict__ hid,
    const float* __restrict__ Wq,
    const float* __restrict__ Wk,
    const float* __restrict__ Wv)
{
    extern __shared__ uint32_t sm32[];

    const int z = blockIdx.z;
    const float* W = (z == 0) ? Wq : (z == 1) ? Wk : Wv;
    float* C = (z == 0) ? g_q : (z == 1) ? g_k : g_v;

    const int m0 = blockIdx.y * 128;
    const int n0 = blockIdx.x * 128;
    const int tid = threadIdx.x;
    const int lane = tid & 31;
    const int warp = tid >> 5;
    const int wm = warp & 1;
    const int wn = warp >> 1;

    const int rA = tid >> 3;
    const int fA = tid & 7;
    const int n4 = tid & 31;
    const int kp2 = tid >> 5;

    float acc[4][4][4];
    #pragma unroll
    for (int i = 0; i < 4; i++)
        #pragma unroll
        for (int j = 0; j < 4; j++)
            #pragma unroll
            for (int r = 0; r < 4; r++) acc[i][j][r] = 0.f;

    float4 pa[4], pb[4];

    #pragma unroll
    for (int j = 0; j < 4; j++)
        pa[j] = *(const float4*)&hid[(long)(m0 + rA + 32 * j) * 1024 + fA * 4];
    #pragma unroll
    for (int t = 0; t < 2; t++) {
        int kp = kp2 + 8 * t;
        pb[2 * t + 0] = *(const float4*)&W[(long)(2 * kp + 0) * 1024 + n0 + n4 * 4];
        pb[2 * t + 1] = *(const float4*)&W[(long)(2 * kp + 1) * 1024 + n0 + n4 * 4];
    }

    int buf = 0;
    {
        uint32_t* Ah = sm32;            uint32_t* Al = sm32 + QUAD_;
        uint32_t* Bh = sm32 + 2*QUAD_;  uint32_t* Bl = sm32 + 3*QUAD_;
        #pragma unroll
        for (int j = 0; j < 4; j++) {
            uint32_t h0, l0, h1, l1;
            split2_pack(pa[j].x, pa[j].y, h0, l0);
            split2_pack(pa[j].z, pa[j].w, h1, l1);
            int r = rA + 32 * j;
            Ah[(fA*2 + 0) * AW_ + r] = h0;
            Ah[(fA*2 + 1) * AW_ + r] = h1;
            Al[(fA*2 + 0) * AW_ + r] = l0;
            Al[(fA*2 + 1) * AW_ + r] = l1;
        }
        #pragma unroll
        for (int t = 0; t < 2; t++) {
            int kp = kp2 + 8 * t;
            float4 e = pb[2*t], o = pb[2*t+1];
            uint4 wh, wl;
            split2_pack(e.x, o.x, wh.x, wl.x);
            split2_pack(e.y, o.y, wh.y, wl.y);
            split2_pack(e.z, o.z, wh.z, wl.z);
            split2_pack(e.w, o.w, wh.w, wl.w);
            *(uint4*)&Bh[kp * AW_ + n4 * 4] = wh;
            *(uint4*)&Bl[kp * AW_ + n4 * 4] = wl;
        }
    }
    __syncthreads();

    const int kq = lane & 3;
    const int ml = lane >> 2;

    for (int kt = 0; kt < 32; kt++) {
        if (kt < 31) {
            int k0 = (kt + 1) * 32;
            #pragma unroll
            for (int j = 0; j < 4; j++)
                pa[j] = *(const float4*)&hid[(long)(m0 + rA + 32 * j) * 1024 + k0 + fA * 4];
            #pragma unroll
            for (int t = 0; t < 2; t++) {
                int kp = kp2 + 8 * t;
                pb[2*t+0] = *(const float4*)&W[(long)(k0 + 2*kp + 0) * 1024 + n0 + n4 * 4];
                pb[2*t+1] = *(const float4*)&W[(long)(k0 + 2*kp + 1) * 1024 + n0 + n4 * 4];
            }
        }

        uint32_t* base = sm32 + buf * BUFW_;
        uint32_t* Ah = base;             uint32_t* Al = base + QUAD_;
        uint32_t* Bh = base + 2*QUAD_;   uint32_t* Bl = base + 3*QUAD_;

        #pragma unroll
        for (int ks = 0; ks < 2; ks++) {
            const int kb = ks * 8;
            uint32_t ah[4][4], al[4][4], bh[4][2], bl[4][2];
            #pragma unroll
            for (int i = 0; i < 4; i++) {
                int mr = wm * 64 + i * 16 + ml;
                ah[i][0] = Ah[(kb + kq) * AW_ + mr];
                ah[i][1] = Ah[(kb + kq) * AW_ + mr + 8];
                ah[i][2] = Ah[(kb + kq + 4) * AW_ + mr];
                ah[i][3] = Ah[(kb + kq + 4) * AW_ + mr + 8];
                al[i][0] = Al[(kb + kq) * AW_ + mr];
                al[i][1] = Al[(kb + kq) * AW_ + mr + 8];
                al[i][2] = Al[(kb + kq + 4) * AW_ + mr];
                al[i][3] = Al[(kb + kq + 4) * AW_ + mr + 8];
            }
            #pragma unroll
            for (int j = 0; j < 4; j++) {
                int nc = wn * 32 + j * 8 + ml;
                bh[j][0] = Bh[(kb + kq) * AW_ + nc];
                bh[j][1] = Bh[(kb + kq + 4) * AW_ + nc];
                bl[j][0] = Bl[(kb + kq) * AW_ + nc];
                bl[j][1] = Bl[(kb + kq + 4) * AW_ + nc];
            }
            #pragma unroll
            for (int i = 0; i < 4; i++)
                #pragma unroll
                for (int j = 0; j < 4; j++) {
                    mma_bf16(acc[i][j], ah[i], bh[j]);
                    mma_bf16(acc[i][j], ah[i], bl[j]);
                    mma_bf16(acc[i][j], al[i], bh[j]);
                }
        }

        if (kt < 31) {
            uint32_t* nb = sm32 + (buf ^ 1) * BUFW_;
            uint32_t* nAh = nb;             uint32_t* nAl = nb + QUAD_;
            uint32_t* nBh = nb + 2*QUAD_;   uint32_t* nBl = nb + 3*QUAD_;
            #pragma unroll
            for (int j = 0; j < 4; j++) {
                uint32_t h0, l0, h1, l1;
                split2_pack(pa[j].x, pa[j].y, h0, l0);
                split2_pack(pa[j].z, pa[j].w, h1, l1);
                int r = rA + 32 * j;
                nAh[(fA*2 + 0) * AW_ + r] = h0;
                nAh[(fA*2 + 1) * AW_ + r] = h1;
                nAl[(fA*2 + 0) * AW_ + r] = l0;
                nAl[(fA*2 + 1) * AW_ + r] = l1;
            }
            #pragma unroll
            for (int t = 0; t < 2; t++) {
                int kp = kp2 + 8 * t;
                float4 e = pb[2*t], o = pb[2*t+1];
                uint4 wh, wl;
                split2_pack(e.x, o.x, wh.x, wl.x);
                split2_pack(e.y, o.y, wh.y, wl.y);
                split2_pack(e.z, o.z, wh.z, wl.z);
                split2_pack(e.w, o.w, wh.w, wl.w);
                *(uint4*)&nBh[kp * AW_ + n4 * 4] = wh;
                *(uint4*)&nBl[kp * AW_ + n4 * 4] = wl;
            }
            __syncthreads();
            buf ^= 1;
        }
    }

    #pragma unroll
    for (int i = 0; i < 4; i++) {
        #pragma unroll
        for (int j = 0; j < 4; j++) {
            int row = m0 + wm * 64 + i * 16 + (lane >> 2);
            int col = n0 + wn * 32 + j * 8 + (lane & 3) * 2;
            float2 c01 = {acc[i][j][0], acc[i][j][1]};
            float2 c23 = {acc[i][j][2], acc[i][j][3]};
            *(float2*)&C[(long)row * 1024 + col] = c01;
            *(float2*)&C[(long)(row + 8) * 1024 + col] = c23;
        }
    }
}

// ---------------------------------------------------------------------------
// Kernel 2: Flash attention, tensor-core bf16 3-pass split for QK^T and PV.
// Grid (N/128, H, B), 256 threads (8 warps), warp = 16 q-rows.
// ---------------------------------------------------------------------------
#define FAW 136     // stride (words) for Q/K arrays [kp][m]
#define FVW 72      // stride (words) for V arrays [kvp][d]
#define FS_QH 0
#define FS_QL (FS_QH + 32*FAW)
#define FS_KH (FS_QL + 32*FAW)
#define FS_KL (FS_KH + 32*FAW)
#define FS_VH (FS_KL + 32*FAW)
#define FS_VL (FS_VH + 64*FVW)
#define FS_TAB (FS_VL + 64*FVW)
#define FLASH_SMEM_BYTES ((FS_TAB + 8) * 4)

__global__ __launch_bounds__(256, 1) void flash_kernel(
    const int* __restrict__ adj,
    const int* __restrict__ relpos,
    const float* __restrict__ rel_table)
{
    extern __shared__ uint32_t fs[];
    float* table = (float*)(fs + FS_TAB);

    const int q0 = blockIdx.x * 128;
    const int h  = blockIdx.y;
    const int b  = blockIdx.z;
    const int tid = threadIdx.x;
    const int lane = tid & 31;
    const int warp = tid >> 5;
    const int qd  = lane & 3;     // quad index (col pair / kp)
    const int ln4 = lane >> 2;    // 0..7
    const int rowA = warp * 16 + ln4;   // fragment row (and rowA+8)

    if (tid < 6) table[tid] = rel_table[tid];

    // ---- load Q (scaled by 1/32), split bf16, [kp][m] layout ----
    const float* qptr = g_q + ((long)b * N_ + q0) * D_ + h * DH_;
    const float scale = 0.03125f;
    #pragma unroll
    for (int it = 0; it < 8; it++) {
        int item = tid + it * 256;          // 0..2047
        int row = (item >> 2) & 127;
        int c4 = (item & 3) + (item >> 9) * 4;   // 0..15
        float4 v = *(const float4*)(qptr + (long)row * D_ + c4 * 4);
        uint32_t h0, l0, h1, l1;
        split2_pack(v.x * scale, v.y * scale, h0, l0);
        split2_pack(v.z * scale, v.w * scale, h1, l1);
        int kp = c4 * 2;
        fs[FS_QH + (kp + 0) * FAW + row] = h0;
        fs[FS_QH + (kp + 1) * FAW + row] = h1;
        fs[FS_QL + (kp + 0) * FAW + row] = l0;
        fs[FS_QL + (kp + 1) * FAW + row] = l1;
    }

    float m0 = -INFINITY, m1 = -INFINITY, l0 = 0.f, l1 = 0.f;
    float o[8][4];
    #pragma unroll
    for (int n = 0; n < 8; n++)
        #pragma unroll
        for (int r = 0; r < 4; r++) o[n][r] = 0.f;

    for (int kt = 0; kt < N_ / 128; kt++) {
        const int kv0 = kt * 128;
        __syncthreads();   // prev tile fully consumed

        // ---- load K tile, split, [kp][kv] ----
        const float* kptr = g_k + ((long)b * N_ + kv0) * D_ + h * DH_;
        #pragma unroll
        for (int it = 0; it < 8; it++) {
            int item = tid + it * 256;
            int row = (item >> 2) & 127;
            int c4 = (item & 3) + (item >> 9) * 4;
            float4 v = *(const float4*)(kptr + (long)row * D_ + c4 * 4);
            uint32_t h0, lo0, h1, lo1;
            split2_pack(v.x, v.y, h0, lo0);
            split2_pack(v.z, v.w, h1, lo1);
            int kp = c4 * 2;
            fs[FS_KH + (kp + 0) * FAW + row] = h0;
            fs[FS_KH + (kp + 1) * FAW + row] = h1;
            fs[FS_KL + (kp + 0) * FAW + row] = lo0;
            fs[FS_KL + (kp + 1) * FAW + row] = lo1;
        }
        // ---- load V tile, split, [kvpair][d] (kv pairs packed in bf16x2) ----
        const float* vptr = g_v + ((long)b * N_ + kv0) * D_ + h * DH_;
        #pragma unroll
        for (int it = 0; it < 4; it++) {
            int idx = tid + it * 256;       // 0..1023
            int r = idx >> 4;               // kv pair 0..63
            int d4 = (idx & 15) * 4;
            const float* p0 = vptr + (long)(2 * r) * D_ + d4;
            float4 va = *(const float4*)p0;
            float4 vb = *(const float4*)(p0 + D_);
            uint4 hh, ll;
            split2_pack(va.x, vb.x, hh.x, ll.x);
            split2_pack(va.y, vb.y, hh.y, ll.y);
            split2_pack(va.z, vb.z, hh.z, ll.z);
            split2_pack(va.w, vb.w, hh.w, ll.w);
            *(uint4*)&fs[FS_VH + r * FVW + d4] = hh;
            *(uint4*)&fs[FS_VL + r * FVW + d4] = ll;
        }
        __syncthreads();

        // ---- S = Q K^T : 16 n-atoms (kv), 4 k-steps (d), 3 passes ----
        float sc[16][4];
        #pragma unroll
        for (int j = 0; j < 16; j++)
            #pragma unroll
            for (int r = 0; r < 4; r++) sc[j][r] = 0.f;

        #pragma unroll
        for (int ks = 0; ks < 4; ks++) {
            const int kb = ks * 8;
            uint32_t ah[4], al[4];
            ah[0] = fs[FS_QH + (kb + qd) * FAW + rowA];
            ah[1] = fs[FS_QH + (kb + qd) * FAW + rowA + 8];
            ah[2] = fs[FS_QH + (kb + qd + 4) * FAW + rowA];
            ah[3] = fs[FS_QH + (kb + qd + 4) * FAW + rowA + 8];
            al[0] = fs[FS_QL + (kb + qd) * FAW + rowA];
            al[1] = fs[FS_QL + (kb + qd) * FAW + rowA + 8];
            al[2] = fs[FS_QL + (kb + qd + 4) * FAW + rowA];
            al[3] = fs[FS_QL + (kb + qd + 4) * FAW + rowA + 8];
            #pragma unroll
            for (int j = 0; j < 16; j++) {
                int nc = j * 8 + ln4;
                uint32_t bh[2], bl[2];
                bh[0] = fs[FS_KH + (kb + qd) * FAW + nc];
                bh[1] = fs[FS_KH + (kb + qd + 4) * FAW + nc];
                bl[0] = fs[FS_KL + (kb + qd) * FAW + nc];
                bl[1] = fs[FS_KL + (kb + qd + 4) * FAW + nc];
                mma_bf16(sc[j], ah, bh);
                mma_bf16(sc[j], ah, bl);
                mma_bf16(sc[j], al, bh);
            }
        }

        // ---- bias + mask ----
        {
            long base0 = ((long)b * N_ + (q0 + rowA)) * N_ + kv0;
            long base1 = base0 + 8 * (long)N_;
            #pragma unroll
            for (int j = 0; j < 16; j++) {
                int c = j * 8 + qd * 2;
                int2 a0 = *(const int2*)(adj + base0 + c);
                int2 r0 = *(const int2*)(relpos + base0 + c);
                int2 a1 = *(const int2*)(adj + base1 + c);
                int2 r1 = *(const int2*)(relpos + base1 + c);
                sc[j][0] = a0.x ? sc[j][0] + table[r0.x] : NEG_INF_;
                sc[j][1] = a0.y ? sc[j][1] + table[r0.y] : NEG_INF_;
                sc[j][2] = a1.x ? sc[j][2] + table[r1.x] : NEG_INF_;
                sc[j][3] = a1.y ? sc[j][3] + table[r1.y] : NEG_INF_;
            }
        }

        // ---- online softmax (rows rowA, rowA+8; quad-reduced) ----
        float t0 = -INFINITY, t1 = -INFINITY;
        #pragma unroll
        for (int j = 0; j < 16; j++) {
            t0 = fmaxf(t0, fmaxf(sc[j][0], sc[j][1]));
            t1 = fmaxf(t1, fmaxf(sc[j][2], sc[j][3]));
        }
        t0 = fmaxf(t0, __shfl_xor_sync(0xffffffffu, t0, 1));
        t0 = fmaxf(t0, __shfl_xor_sync(0xffffffffu, t0, 2));
        t1 = fmaxf(t1, __shfl_xor_sync(0xffffffffu, t1, 1));
        t1 = fmaxf(t1, __shfl_xor_sync(0xffffffffu, t1, 2));
        float m0n = fmaxf(m0, t0), m1n = fmaxf(m1, t1);
        float s0 = __expf(m0 - m0n), s1 = __expf(m1 - m1n);
        #pragma unroll
        for (int n = 0; n < 8; n++) {
            o[n][0] *= s0; o[n][1] *= s0;
            o[n][2] *= s1; o[n][3] *= s1;
        }
        float add0 = 0.f, add1 = 0.f;
        #pragma unroll
        for (int j = 0; j < 16; j++) {
            sc[j][0] = __expf(sc[j][0] - m0n);
            sc[j][1] = __expf(sc[j][1] - m0n);
            sc[j][2] = __expf(sc[j][2] - m1n);
            sc[j][3] = __expf(sc[j][3] - m1n);
            add0 += sc[j][0] + sc[j][1];
            add1 += sc[j][2] + sc[j][3];
        }
        add0 += __shfl_xor_sync(0xffffffffu, add0, 1);
        add0 += __shfl_xor_sync(0xffffffffu, add0, 2);
        add1 += __shfl_xor_sync(0xffffffffu, add1, 1);
        add1 += __shfl_xor_sync(0xffffffffu, add1, 2);
        l0 = l0 * s0 + add0;
        l1 = l1 * s1 + add1;
        m0 = m0n; m1 = m1n;

        // ---- O += P V : P split in regs (C-frag == A-frag layout) ----
        #pragma unroll
        for (int kk = 0; kk < 8; kk++) {
            uint32_t ph[4], pl[4];
            split2_pack(sc[2*kk][0],   sc[2*kk][1],   ph[0], pl[0]);
            split2_pack(sc[2*kk][2],   sc[2*kk][3],   ph[1], pl[1]);
            split2_pack(sc[2*kk+1][0], sc[2*kk+1][1], ph[2], pl[2]);
            split2_pack(sc[2*kk+1][2], sc[2*kk+1][3], ph[3], pl[3]);
            #pragma unroll
            for (int n = 0; n < 8; n++) {
                int nc = n * 8 + ln4;
                uint32_t bh[2], bl[2];
                bh[0] = fs[FS_VH + (kk * 8 + qd) * FVW + nc];
                bh[1] = fs[FS_VH + (kk * 8 + qd + 4) * FVW + nc];
                bl[0] = fs[FS_VL + (kk * 8 + qd) * FVW + nc];
                bl[1] = fs[FS_VL + (kk * 8 + qd + 4) * FVW + nc];
                mma_bf16(o[n], ph, bh);
                mma_bf16(o[n], ph, bl);
                mma_bf16(o[n], pl, bh);
            }
        }
    }

    // ---- finalize: divide by l, write out ----
    float inv0 = 1.f / l0, inv1 = 1.f / l1;
    float* aout = g_ao + ((long)b * N_ + q0) * D_ + h * DH_;
    #pragma unroll
    for (int n = 0; n < 8; n++) {
        int col = n * 8 + qd * 2;
        float2 r0 = {o[n][0] * inv0, o[n][1] * inv0};
        float2 r1 = {o[n][2] * inv1, o[n][3] * inv1};
        *(float2*)(aout + (long)rowA * D_ + col) = r0;
        *(float2*)(aout + (long)(rowA + 8) * D_ + col) = r1;
    }
}

// ---------------------------------------------------------------------------
// Kernel 3: out = LayerNorm(relu(attn_out) + hid) * gamma + beta
// ---------------------------------------------------------------------------
__global__ __launch_bounds__(256) void epilogue_kernel(
    const float* __restrict__ hid,
    const float* __restrict__ gamma,
    const float* __restrict__ beta,
    float* __restrict__ out)
{
    __shared__ float rs[8];
    __shared__ float rq[8];
    __shared__ float stats[2];

    const long row = blockIdx.x;
    const float* a = g_ao + row * D_;
    const float* hp = hid + row * D_;
    const int c = threadIdx.x * 4;

    float4 av = *(const float4*)(a + c);
    float4 hv = *(const float4*)(hp + c);
    float4 y;
    y.x = fmaxf(av.x, 0.f) + hv.x;
    y.y = fmaxf(av.y, 0.f) + hv.y;
    y.z = fmaxf(av.z, 0.f) + hv.z;
    y.w = fmaxf(av.w, 0.f) + hv.w;

    float sum = y.x + y.y + y.z + y.w;
    float sq  = y.x * y.x + y.y * y.y + y.z * y.z + y.w * y.w;
    #pragma unroll
    for (int off = 16; off > 0; off >>= 1) {
        sum += __shfl_xor_sync(0xffffffffu, sum, off);
        sq  += __shfl_xor_sync(0xffffffffu, sq, off);
    }
    if ((threadIdx.x & 31) == 0) {
        rs[threadIdx.x >> 5] = sum;
        rq[threadIdx.x >> 5] = sq;
    }
    __syncthreads();
    if (threadIdx.x == 0) {
        float S = 0.f, Q = 0.f;
        #pragma unroll
        for (int w = 0; w < 8; w++) { S += rs[w]; Q += rq[w]; }
        float mean = S * (1.f / 1024.f);
        float var  = Q * (1.f / 1024.f) - mean * mean;
        stats[0] = mean;
        stats[1] = rsqrtf(var + 1e-5f);
    }
    __syncthreads();
    float mean = stats[0], rstd = stats[1];

    float4 g4 = *(const float4*)(gamma + c);
    float4 b4 = *(const float4*)(beta + c);
    float4 o4;
    o4.x = (y.x - mean) * rstd * g4.x + b4.x;
    o4.y = (y.y - mean) * rstd * g4.y + b4.y;
    o4.z = (y.z - mean) * rstd * g4.z + b4.z;
    o4.w = (y.w - mean) * rstd * g4.w + b4.w;
    *(float4*)(out + row * D_ + c) = o4;
}

// ---------------------------------------------------------------------------
extern "C" void kernel_launch(void* const* d_in, const int* in_sizes, int n_in,
                              void* d_out, int out_size)
{
    const float* hid      = (const float*)d_in[0];
    const int*   adj      = (const int*)d_in[1];
    const int*   relpos   = (const int*)d_in[2];
    const float* Wq       = (const float*)d_in[3];
    const float* Wk       = (const float*)d_in[4];
    const float* Wv       = (const float*)d_in[5];
    const float* rel_tab  = (const float*)d_in[6];
    const float* gamma    = (const float*)d_in[7];
    const float* beta     = (const float*)d_in[8];
    float* out = (float*)d_out;

    cudaFuncSetAttribute(qkv_gemm_kernel,
                         cudaFuncAttributeMaxDynamicSharedMemorySize,
                         GEMM_SMEM_BYTES);
    dim3 ggrid(1024 / 128, 8192 / 128, 3);
    qkv_gemm_kernel<<<ggrid, 256, GEMM_SMEM_BYTES>>>(hid, Wq, Wk, Wv);

    cudaFuncSetAttribute(flash_kernel,
                         cudaFuncAttributeMaxDynamicSharedMemorySize,
                         FLASH_SMEM_BYTES);
    dim3 fgrid(N_ / 128, H_, B_);
    flash_kernel<<<fgrid, 256, FLASH_SMEM_BYTES>>>(adj, relpos, rel_tab);

    epilogue_kernel<<<B_ * N_, 256>>>(hid, gamma, beta, out);
}

// round 5
// speedup vs baseline: 2.5137x; 1.6155x over previous
#include <cuda_runtime.h>
#include <cuda_bf16.h>
#include <cstdint>
#include <math.h>

#define B_  8
#define N_  1024
#define D_  1024
#define H_  16
#define DH_ 64
#define NEG_INF_ (-1e9f)

// Scratch (device globals — no allocation allowed)
__device__ float g_q[B_*N_*D_];
__device__ float g_k[B_*N_*D_];
__device__ float g_v[B_*N_*D_];
__device__ float g_ao[B_*N_*D_];
__device__ float g_bias[B_*N_*N_];

// ---------------------------------------------------------------------------
// Shared helpers: bf16 split + m16n8k16 mma
// ---------------------------------------------------------------------------
__device__ __forceinline__ uint32_t pack_bf16(float x, float y) {
    __nv_bfloat162 t = __floats2bfloat162_rn(x, y);
    return *(uint32_t*)&t;
}
__device__ __forceinline__ void split_bf16(float x, float& hi, float& lo) {
    __nv_bfloat16 h = __float2bfloat16_rn(x);
    hi = __bfloat162float(h);
    lo = x - hi;
}
__device__ __forceinline__ void split2_pack(float x, float y, uint32_t& hi, uint32_t& lo) {
    float hx, lx, hy, ly;
    split_bf16(x, hx, lx); split_bf16(y, hy, ly);
    hi = pack_bf16(hx, hy); lo = pack_bf16(lx, ly);
}
__device__ __forceinline__ void mma_bf16(float* d, const uint32_t* a, const uint32_t* b) {
    asm volatile(
        "mma.sync.aligned.m16n8k16.row.col.f32.bf16.bf16.f32 "
        "{%0,%1,%2,%3}, {%4,%5,%6,%7}, {%8,%9}, {%0,%1,%2,%3};\n"
        : "+f"(d[0]), "+f"(d[1]), "+f"(d[2]), "+f"(d[3])
        : "r"(a[0]), "r"(a[1]), "r"(a[2]), "r"(a[3]), "r"(b[0]), "r"(b[1]));
}

// ---------------------------------------------------------------------------
// Kernel 0: bias precompute.  g_bias = adj ? table[relpos] : -1e9
// ---------------------------------------------------------------------------
__global__ __launch_bounds__(256) void bias_kernel(
    const int* __restrict__ adj,
    const int* __restrict__ relpos,
    const float* __restrict__ rel_table)
{
    __shared__ float t[8];
    if (threadIdx.x < 6) t[threadIdx.x] = rel_table[threadIdx.x];
    __syncthreads();
    long i4 = (long)blockIdx.x * 256 + threadIdx.x;
    int4 a = *(const int4*)(adj + i4 * 4);
    int4 r = *(const int4*)(relpos + i4 * 4);
    float4 o;
    o.x = a.x ? t[r.x] : NEG_INF_;
    o.y = a.y ? t[r.y] : NEG_INF_;
    o.z = a.z ? t[r.z] : NEG_INF_;
    o.w = a.w ? t[r.w] : NEG_INF_;
    *(float4*)(g_bias + i4 * 4) = o;
}

// ---------------------------------------------------------------------------
// Kernel 1: QKV projection with bf16-split tensor-core MMA. (unchanged)
// ---------------------------------------------------------------------------
#define AW_ 136
#define QUAD_ (16 * AW_)
#define BUFW_ (4 * QUAD_)
#define GEMM_SMEM_BYTES (2 * BUFW_ * 4)

__global__ __launch_bounds__(256, 1) void qkv_gemm_kernel(
    const float* __restrict__ hid,
    const float* __restrict__ Wq,
    const float* __restrict__ Wk,
    const float* __restrict__ Wv)
{
    extern __shared__ uint32_t sm32[];

    const int z = blockIdx.z;
    const float* W = (z == 0) ? Wq : (z == 1) ? Wk : Wv;
    float* C = (z == 0) ? g_q : (z == 1) ? g_k : g_v;

    const int m0 = blockIdx.y * 128;
    const int n0 = blockIdx.x * 128;
    const int tid = threadIdx.x;
    const int lane = tid & 31;
    const int warp = tid >> 5;
    const int wm = warp & 1;
    const int wn = warp >> 1;

    const int rA = tid >> 3;
    const int fA = tid & 7;
    const int n4 = tid & 31;
    const int kp2 = tid >> 5;

    float acc[4][4][4];
    #pragma unroll
    for (int i = 0; i < 4; i++)
        #pragma unroll
        for (int j = 0; j < 4; j++)
            #pragma unroll
            for (int r = 0; r < 4; r++) acc[i][j][r] = 0.f;

    float4 pa[4], pb[4];

    #pragma unroll
    for (int j = 0; j < 4; j++)
        pa[j] = *(const float4*)&hid[(long)(m0 + rA + 32 * j) * 1024 + fA * 4];
    #pragma unroll
    for (int t = 0; t < 2; t++) {
        int kp = kp2 + 8 * t;
        pb[2 * t + 0] = *(const float4*)&W[(long)(2 * kp + 0) * 1024 + n0 + n4 * 4];
        pb[2 * t + 1] = *(const float4*)&W[(long)(2 * kp + 1) * 1024 + n0 + n4 * 4];
    }

    int buf = 0;
    {
        uint32_t* Ah = sm32;            uint32_t* Al = sm32 + QUAD_;
        uint32_t* Bh = sm32 + 2*QUAD_;  uint32_t* Bl = sm32 + 3*QUAD_;
        #pragma unroll
        for (int j = 0; j < 4; j++) {
            uint32_t h0, l0, h1, l1;
            split2_pack(pa[j].x, pa[j].y, h0, l0);
            split2_pack(pa[j].z, pa[j].w, h1, l1);
            int r = rA + 32 * j;
            Ah[(fA*2 + 0) * AW_ + r] = h0;
            Ah[(fA*2 + 1) * AW_ + r] = h1;
            Al[(fA*2 + 0) * AW_ + r] = l0;
            Al[(fA*2 + 1) * AW_ + r] = l1;
        }
        #pragma unroll
        for (int t = 0; t < 2; t++) {
            int kp = kp2 + 8 * t;
            float4 e = pb[2*t], o = pb[2*t+1];
            uint4 wh, wl;
            split2_pack(e.x, o.x, wh.x, wl.x);
            split2_pack(e.y, o.y, wh.y, wl.y);
            split2_pack(e.z, o.z, wh.z, wl.z);
            split2_pack(e.w, o.w, wh.w, wl.w);
            *(uint4*)&Bh[kp * AW_ + n4 * 4] = wh;
            *(uint4*)&Bl[kp * AW_ + n4 * 4] = wl;
        }
    }
    __syncthreads();

    const int kq = lane & 3;
    const int ml = lane >> 2;

    for (int kt = 0; kt < 32; kt++) {
        if (kt < 31) {
            int k0 = (kt + 1) * 32;
            #pragma unroll
            for (int j = 0; j < 4; j++)
                pa[j] = *(const float4*)&hid[(long)(m0 + rA + 32 * j) * 1024 + k0 + fA * 4];
            #pragma unroll
            for (int t = 0; t < 2; t++) {
                int kp = kp2 + 8 * t;
                pb[2*t+0] = *(const float4*)&W[(long)(k0 + 2*kp + 0) * 1024 + n0 + n4 * 4];
                pb[2*t+1] = *(const float4*)&W[(long)(k0 + 2*kp + 1) * 1024 + n0 + n4 * 4];
            }
        }

        uint32_t* base = sm32 + buf * BUFW_;
        uint32_t* Ah = base;             uint32_t* Al = base + QUAD_;
        uint32_t* Bh = base + 2*QUAD_;   uint32_t* Bl = base + 3*QUAD_;

        #pragma unroll
        for (int ks = 0; ks < 2; ks++) {
            const int kb = ks * 8;
            uint32_t ah[4][4], al[4][4], bh[4][2], bl[4][2];
            #pragma unroll
            for (int i = 0; i < 4; i++) {
                int mr = wm * 64 + i * 16 + ml;
                ah[i][0] = Ah[(kb + kq) * AW_ + mr];
                ah[i][1] = Ah[(kb + kq) * AW_ + mr + 8];
                ah[i][2] = Ah[(kb + kq + 4) * AW_ + mr];
                ah[i][3] = Ah[(kb + kq + 4) * AW_ + mr + 8];
                al[i][0] = Al[(kb + kq) * AW_ + mr];
                al[i][1] = Al[(kb + kq) * AW_ + mr + 8];
                al[i][2] = Al[(kb + kq + 4) * AW_ + mr];
                al[i][3] = Al[(kb + kq + 4) * AW_ + mr + 8];
            }
            #pragma unroll
            for (int j = 0; j < 4; j++) {
                int nc = wn * 32 + j * 8 + ml;
                bh[j][0] = Bh[(kb + kq) * AW_ + nc];
                bh[j][1] = Bh[(kb + kq + 4) * AW_ + nc];
                bl[j][0] = Bl[(kb + kq) * AW_ + nc];
                bl[j][1] = Bl[(kb + kq + 4) * AW_ + nc];
            }
            #pragma unroll
            for (int i = 0; i < 4; i++)
                #pragma unroll
                for (int j = 0; j < 4; j++) {
                    mma_bf16(acc[i][j], ah[i], bh[j]);
                    mma_bf16(acc[i][j], ah[i], bl[j]);
                    mma_bf16(acc[i][j], al[i], bh[j]);
                }
        }

        if (kt < 31) {
            uint32_t* nb = sm32 + (buf ^ 1) * BUFW_;
            uint32_t* nAh = nb;             uint32_t* nAl = nb + QUAD_;
            uint32_t* nBh = nb + 2*QUAD_;   uint32_t* nBl = nb + 3*QUAD_;
            #pragma unroll
            for (int j = 0; j < 4; j++) {
                uint32_t h0, l0, h1, l1;
                split2_pack(pa[j].x, pa[j].y, h0, l0);
                split2_pack(pa[j].z, pa[j].w, h1, l1);
                int r = rA + 32 * j;
                nAh[(fA*2 + 0) * AW_ + r] = h0;
                nAh[(fA*2 + 1) * AW_ + r] = h1;
                nAl[(fA*2 + 0) * AW_ + r] = l0;
                nAl[(fA*2 + 1) * AW_ + r] = l1;
            }
            #pragma unroll
            for (int t = 0; t < 2; t++) {
                int kp = kp2 + 8 * t;
                float4 e = pb[2*t], o = pb[2*t+1];
                uint4 wh, wl;
                split2_pack(e.x, o.x, wh.x, wl.x);
                split2_pack(e.y, o.y, wh.y, wl.y);
                split2_pack(e.z, o.z, wh.z, wl.z);
                split2_pack(e.w, o.w, wh.w, wl.w);
                *(uint4*)&nBh[kp * AW_ + n4 * 4] = wh;
                *(uint4*)&nBl[kp * AW_ + n4 * 4] = wl;
            }
            __syncthreads();
            buf ^= 1;
        }
    }

    #pragma unroll
    for (int i = 0; i < 4; i++) {
        #pragma unroll
        for (int j = 0; j < 4; j++) {
            int row = m0 + wm * 64 + i * 16 + (lane >> 2);
            int col = n0 + wn * 32 + j * 8 + (lane & 3) * 2;
            float2 c01 = {acc[i][j][0], acc[i][j][1]};
            float2 c23 = {acc[i][j][2], acc[i][j][3]};
            *(float2*)&C[(long)row * 1024 + col] = c01;
            *(float2*)&C[(long)(row + 8) * 1024 + col] = c23;
        }
    }
}

// ---------------------------------------------------------------------------
// Kernel 2: Flash attention, tensor-core bf16, pair-interleaved smem (LDS.64),
// precomputed fp32 bias, P in plain bf16 (2-pass PV).
// Grid (N/128, H, B), 256 threads (8 warps), warp = 16 q-rows.
// ---------------------------------------------------------------------------
#define U2Q 132                    // uint2 stride for Q/K arrays [slot][row]
#define U2V 68                     // uint2 stride for V arrays [slot][col]
#define QH2 0
#define QL2 (QH2 + 16*U2Q)
#define KH2 (QL2 + 16*U2Q)
#define KL2 (KH2 + 16*U2Q)
#define VH2 (KL2 + 16*U2Q)
#define VL2 (VH2 + 32*U2V)
#define FLASH_U2_TOTAL (VL2 + 32*U2V)
#define FLASH_SMEM_BYTES (FLASH_U2_TOTAL * 8)

__global__ __launch_bounds__(256, 1) void flash_kernel(
    const float* __restrict__ bias)
{
    extern __shared__ uint2 fs2[];
    uint32_t* fw = (uint32_t*)fs2;

    const int q0 = blockIdx.x * 128;
    const int h  = blockIdx.y;
    const int b  = blockIdx.z;
    const int tid = threadIdx.x;
    const int lane = tid & 31;
    const int warp = tid >> 5;
    const int qd  = lane & 3;     // quad index (col pair / kp)
    const int ln4 = lane >> 2;    // 0..7
    const int rowA = warp * 16 + ln4;   // fragment row (and rowA+8)

    // ---- load Q (scaled by 1/32), split bf16, pair-interleaved [slot][row] ----
    const float* qptr = g_q + ((long)b * N_ + q0) * D_ + h * DH_;
    const float scale = 0.03125f;
    #pragma unroll
    for (int it = 0; it < 8; it++) {
        int item = tid + it * 256;          // 0..2047
        int row = (item >> 2) & 127;
        int c4 = (item & 3) + (item >> 9) * 4;   // 0..15
        float4 v = *(const float4*)(qptr + (long)row * D_ + c4 * 4);
        uint32_t h0, l0, h1, l1;
        split2_pack(v.x * scale, v.y * scale, h0, l0);
        split2_pack(v.z * scale, v.w * scale, h1, l1);
        int kp0 = 2 * c4, kp1 = 2 * c4 + 1;
        int w0 = 2 * ((((kp0 >> 3) << 2) + (kp0 & 3)) * U2Q + row) + ((kp0 >> 2) & 1);
        int w1 = 2 * ((((kp1 >> 3) << 2) + (kp1 & 3)) * U2Q + row) + ((kp1 >> 2) & 1);
        fw[QH2 * 2 + w0] = h0;
        fw[QH2 * 2 + w1] = h1;
        fw[QL2 * 2 + w0] = l0;
        fw[QL2 * 2 + w1] = l1;
    }

    float m0 = -INFINITY, m1 = -INFINITY, l0 = 0.f, l1 = 0.f;
    float o[8][4];
    #pragma unroll
    for (int n = 0; n < 8; n++)
        #pragma unroll
        for (int r = 0; r < 4; r++) o[n][r] = 0.f;

    for (int kt = 0; kt < N_ / 128; kt++) {
        const int kv0 = kt * 128;
        __syncthreads();   // prev tile fully consumed

        // ---- load K tile, split, pair-interleaved ----
        const float* kptr = g_k + ((long)b * N_ + kv0) * D_ + h * DH_;
        #pragma unroll
        for (int it = 0; it < 8; it++) {
            int item = tid + it * 256;
            int row = (item >> 2) & 127;
            int c4 = (item & 3) + (item >> 9) * 4;
            float4 v = *(const float4*)(kptr + (long)row * D_ + c4 * 4);
            uint32_t h0, lo0, h1, lo1;
            split2_pack(v.x, v.y, h0, lo0);
            split2_pack(v.z, v.w, h1, lo1);
            int kp0 = 2 * c4, kp1 = 2 * c4 + 1;
            int w0 = 2 * ((((kp0 >> 3) << 2) + (kp0 & 3)) * U2Q + row) + ((kp0 >> 2) & 1);
            int w1 = 2 * ((((kp1 >> 3) << 2) + (kp1 & 3)) * U2Q + row) + ((kp1 >> 2) & 1);
            fw[KH2 * 2 + w0] = h0;
            fw[KH2 * 2 + w1] = h1;
            fw[KL2 * 2 + w0] = lo0;
            fw[KL2 * 2 + w1] = lo1;
        }
        // ---- load V tile, split, pair-interleaved [slot][col] ----
        const float* vptr = g_v + ((long)b * N_ + kv0) * D_ + h * DH_;
        #pragma unroll
        for (int it = 0; it < 4; it++) {
            int idx = tid + it * 256;       // 0..1023
            int r = idx >> 4;               // kv pair 0..63
            int d4 = (idx & 15) * 4;
            const float* p0 = vptr + (long)(2 * r) * D_ + d4;
            float4 va = *(const float4*)p0;
            float4 vb = *(const float4*)(p0 + D_);
            uint32_t hh[4], ll[4];
            split2_pack(va.x, vb.x, hh[0], ll[0]);
            split2_pack(va.y, vb.y, hh[1], ll[1]);
            split2_pack(va.z, vb.z, hh[2], ll[2]);
            split2_pack(va.w, vb.w, hh[3], ll[3]);
            int sv = ((r >> 3) << 2) + (r & 3);
            int hv = (r >> 2) & 1;
            #pragma unroll
            for (int d = 0; d < 4; d++) {
                int w = 2 * (sv * U2V + d4 + d) + hv;
                fw[VH2 * 2 + w] = hh[d];
                fw[VL2 * 2 + w] = ll[d];
            }
        }
        __syncthreads();

        // ---- S = Q K^T : 16 n-atoms (kv), 4 k-steps (d), 3 passes ----
        float sc[16][4];
        #pragma unroll
        for (int j = 0; j < 16; j++)
            #pragma unroll
            for (int r = 0; r < 4; r++) sc[j][r] = 0.f;

        #pragma unroll
        for (int ks = 0; ks < 4; ks++) {
            const int slot = ks * 4 + qd;
            uint2 a0h = fs2[QH2 + slot * U2Q + rowA];
            uint2 a1h = fs2[QH2 + slot * U2Q + rowA + 8];
            uint2 a0l = fs2[QL2 + slot * U2Q + rowA];
            uint2 a1l = fs2[QL2 + slot * U2Q + rowA + 8];
            uint32_t ah[4] = {a0h.x, a1h.x, a0h.y, a1h.y};
            uint32_t al[4] = {a0l.x, a1l.x, a0l.y, a1l.y};
            #pragma unroll
            for (int j = 0; j < 16; j++) {
                int nc = j * 8 + ln4;
                uint2 bhu = fs2[KH2 + slot * U2Q + nc];
                uint2 blu = fs2[KL2 + slot * U2Q + nc];
                uint32_t bh[2] = {bhu.x, bhu.y};
                uint32_t bl[2] = {blu.x, blu.y};
                mma_bf16(sc[j], ah, bh);
                mma_bf16(sc[j], ah, bl);
                mma_bf16(sc[j], al, bh);
            }
        }

        // ---- add precomputed bias (handles mask) ----
        {
            long base0 = ((long)b * N_ + (q0 + rowA)) * N_ + kv0;
            long base1 = base0 + 8 * (long)N_;
            #pragma unroll
            for (int j = 0; j < 16; j++) {
                int c = j * 8 + qd * 2;
                float2 b0 = *(const float2*)(bias + base0 + c);
                float2 b1 = *(const float2*)(bias + base1 + c);
                sc[j][0] += b0.x; sc[j][1] += b0.y;
                sc[j][2] += b1.x; sc[j][3] += b1.y;
            }
        }

        // ---- online softmax (rows rowA, rowA+8; quad-reduced) ----
        float t0 = -INFINITY, t1 = -INFINITY;
        #pragma unroll
        for (int j = 0; j < 16; j++) {
            t0 = fmaxf(t0, fmaxf(sc[j][0], sc[j][1]));
            t1 = fmaxf(t1, fmaxf(sc[j][2], sc[j][3]));
        }
        t0 = fmaxf(t0, __shfl_xor_sync(0xffffffffu, t0, 1));
        t0 = fmaxf(t0, __shfl_xor_sync(0xffffffffu, t0, 2));
        t1 = fmaxf(t1, __shfl_xor_sync(0xffffffffu, t1, 1));
        t1 = fmaxf(t1, __shfl_xor_sync(0xffffffffu, t1, 2));
        float m0n = fmaxf(m0, t0), m1n = fmaxf(m1, t1);
        float s0 = __expf(m0 - m0n), s1 = __expf(m1 - m1n);
        #pragma unroll
        for (int n = 0; n < 8; n++) {
            o[n][0] *= s0; o[n][1] *= s0;
            o[n][2] *= s1; o[n][3] *= s1;
        }
        float add0 = 0.f, add1 = 0.f;
        #pragma unroll
        for (int j = 0; j < 16; j++) {
            sc[j][0] = __expf(sc[j][0] - m0n);
            sc[j][1] = __expf(sc[j][1] - m0n);
            sc[j][2] = __expf(sc[j][2] - m1n);
            sc[j][3] = __expf(sc[j][3] - m1n);
            add0 += sc[j][0] + sc[j][1];
            add1 += sc[j][2] + sc[j][3];
        }
        add0 += __shfl_xor_sync(0xffffffffu, add0, 1);
        add0 += __shfl_xor_sync(0xffffffffu, add0, 2);
        add1 += __shfl_xor_sync(0xffffffffu, add1, 1);
        add1 += __shfl_xor_sync(0xffffffffu, add1, 2);
        l0 = l0 * s0 + add0;
        l1 = l1 * s1 + add1;
        m0 = m0n; m1 = m1n;

        // ---- O += P V : P plain bf16 (C-frag == A-frag layout), V split ----
        #pragma unroll
        for (int kk = 0; kk < 8; kk++) {
            uint32_t ph[4];
            ph[0] = pack_bf16(sc[2*kk][0],   sc[2*kk][1]);
            ph[1] = pack_bf16(sc[2*kk][2],   sc[2*kk][3]);
            ph[2] = pack_bf16(sc[2*kk+1][0], sc[2*kk+1][1]);
            ph[3] = pack_bf16(sc[2*kk+1][2], sc[2*kk+1][3]);
            const int svb = kk * 4 + qd;
            #pragma unroll
            for (int n = 0; n < 8; n++) {
                int nc = n * 8 + ln4;
                uint2 bhu = fs2[VH2 + svb * U2V + nc];
                uint2 blu = fs2[VL2 + svb * U2V + nc];
                uint32_t bh[2] = {bhu.x, bhu.y};
                uint32_t bl[2] = {blu.x, blu.y};
                mma_bf16(o[n], ph, bh);
                mma_bf16(o[n], ph, bl);
            }
        }
    }

    // ---- finalize: divide by l, write out ----
    float inv0 = 1.f / l0, inv1 = 1.f / l1;
    float* aout = g_ao + ((long)b * N_ + q0) * D_ + h * DH_;
    #pragma unroll
    for (int n = 0; n < 8; n++) {
        int col = n * 8 + qd * 2;
        float2 r0 = {o[n][0] * inv0, o[n][1] * inv0};
        float2 r1 = {o[n][2] * inv1, o[n][3] * inv1};
        *(float2*)(aout + (long)rowA * D_ + col) = r0;
        *(float2*)(aout + (long)(rowA + 8) * D_ + col) = r1;
    }
}

// ---------------------------------------------------------------------------
// Kernel 3: out = LayerNorm(relu(attn_out) + hid) * gamma + beta
// ---------------------------------------------------------------------------
__global__ __launch_bounds__(256) void epilogue_kernel(
    const float* __restrict__ hid,
    const float* __restrict__ gamma,
    const float* __restrict__ beta,
    float* __restrict__ out)
{
    __shared__ float rs[8];
    __shared__ float rq[8];
    __shared__ float stats[2];

    const long row = blockIdx.x;
    const float* a = g_ao + row * D_;
    const float* hp = hid + row * D_;
    const int c = threadIdx.x * 4;

    float4 av = *(const float4*)(a + c);
    float4 hv = *(const float4*)(hp + c);
    float4 y;
    y.x = fmaxf(av.x, 0.f) + hv.x;
    y.y = fmaxf(av.y, 0.f) + hv.y;
    y.z = fmaxf(av.z, 0.f) + hv.z;
    y.w = fmaxf(av.w, 0.f) + hv.w;

    float sum = y.x + y.y + y.z + y.w;
    float sq  = y.x * y.x + y.y * y.y + y.z * y.z + y.w * y.w;
    #pragma unroll
    for (int off = 16; off > 0; off >>= 1) {
        sum += __shfl_xor_sync(0xffffffffu, sum, off);
        sq  += __shfl_xor_sync(0xffffffffu, sq, off);
    }
    if ((threadIdx.x & 31) == 0) {
        rs[threadIdx.x >> 5] = sum;
        rq[threadIdx.x >> 5] = sq;
    }
    __syncthreads();
    if (threadIdx.x == 0) {
        float S = 0.f, Q = 0.f;
        #pragma unroll
        for (int w = 0; w < 8; w++) { S += rs[w]; Q += rq[w]; }
        float mean = S * (1.f / 1024.f);
        float var  = Q * (1.f / 1024.f) - mean * mean;
        stats[0] = mean;
        stats[1] = rsqrtf(var + 1e-5f);
    }
    __syncthreads();
    float mean = stats[0], rstd = stats[1];

    float4 g4 = *(const float4*)(gamma + c);
    float4 b4 = *(const float4*)(beta + c);
    float4 o4;
    o4.x = (y.x - mean) * rstd * g4.x + b4.x;
    o4.y = (y.y - mean) * rstd * g4.y + b4.y;
    o4.z = (y.z - mean) * rstd * g4.z + b4.z;
    o4.w = (y.w - mean) * rstd * g4.w + b4.w;
    *(float4*)(out + row * D_ + c) = o4;
}

// ---------------------------------------------------------------------------
extern "C" void kernel_launch(void* const* d_in, const int* in_sizes, int n_in,
                              void* d_out, int out_size)
{
    const float* hid      = (const float*)d_in[0];
    const int*   adj      = (const int*)d_in[1];
    const int*   relpos   = (const int*)d_in[2];
    const float* Wq       = (const float*)d_in[3];
    const float* Wk       = (const float*)d_in[4];
    const float* Wv       = (const float*)d_in[5];
    const float* rel_tab  = (const float*)d_in[6];
    const float* gamma    = (const float*)d_in[7];
    const float* beta     = (const float*)d_in[8];
    float* out = (float*)d_out;

    bias_kernel<<<B_ * N_ * N_ / 1024, 256>>>(adj, relpos, rel_tab);

    cudaFuncSetAttribute(qkv_gemm_kernel,
                         cudaFuncAttributeMaxDynamicSharedMemorySize,
                         GEMM_SMEM_BYTES);
    dim3 ggrid(1024 / 128, 8192 / 128, 3);
    qkv_gemm_kernel<<<ggrid, 256, GEMM_SMEM_BYTES>>>(hid, Wq, Wk, Wv);

    // resolve g_bias device address for flash kernel
    float* bias_ptr = nullptr;
    cudaGetSymbolAddress((void**)&bias_ptr, g_bias);

    cudaFuncSetAttribute(flash_kernel,
                         cudaFuncAttributeMaxDynamicSharedMemorySize,
                         FLASH_SMEM_BYTES);
    dim3 fgrid(N_ / 128, H_, B_);
    flash_kernel<<<fgrid, 256, FLASH_SMEM_BYTES>>>(bias_ptr);

    epilogue_kernel<<<B_ * N_, 256>>>(hid, gamma, beta, out);
}